// round 2
// baseline (speedup 1.0000x reference)
#include <cuda_runtime.h>
#include <cstdint>

// Problem constants (Head_84533546320520)
#define BATCH 8
#define SEQ   2048
#define DEMB  1024
#define HEAD  64
#define NROWS (BATCH * SEQ)   // 16384
#define SCALE 0.125f          // HEAD^-0.5

// Scratch for projected q/k/v: [B*S, 64] each, fp32 (4 MB each)
__device__ float g_qp[NROWS * HEAD];
__device__ float g_kp[NROWS * HEAD];
__device__ float g_vp[NROWS * HEAD];

// ---------------------------------------------------------------------------
// Kernel 1: projections. grid = (NROWS/64, 3), block = 256.
// Tiled GEMM: C[64,64] = X[64,1024] @ W[1024,64], BK = 32.
// ---------------------------------------------------------------------------
__global__ __launch_bounds__(256) void proj_kernel(
    const float* __restrict__ q, const float* __restrict__ k,
    const float* __restrict__ v,
    const float* __restrict__ Wq, const float* __restrict__ Wk,
    const float* __restrict__ Wv)
{
    const int which = blockIdx.y;
    const float* __restrict__ x = (which == 0) ? q : (which == 1) ? k : v;
    const float* __restrict__ W = (which == 0) ? Wq : (which == 1) ? Wk : Wv;
    float* __restrict__ out     = (which == 0) ? g_qp : (which == 1) ? g_kp : g_vp;

    __shared__ float As[32][68];   // [k][m], padded
    __shared__ float Bs[32][64];   // [k][n]

    const int tid = threadIdx.x;
    const int tx = tid & 15;        // output col group (n)
    const int ty = tid >> 4;        // output row group (m)
    const int row0 = blockIdx.x * 64;

    float acc[4][4] = {};

    for (int k0 = 0; k0 < DEMB; k0 += 32) {
        #pragma unroll
        for (int i = 0; i < 2; i++) {
            int idx = tid + i * 256;          // 0..511
            int m   = idx >> 3;               // 0..63
            int kq  = idx & 7;                // 0..7
            float4 t = *reinterpret_cast<const float4*>(
                x + (size_t)(row0 + m) * DEMB + k0 + kq * 4);
            As[kq * 4 + 0][m] = t.x;
            As[kq * 4 + 1][m] = t.y;
            As[kq * 4 + 2][m] = t.z;
            As[kq * 4 + 3][m] = t.w;
        }
        #pragma unroll
        for (int i = 0; i < 2; i++) {
            int idx = tid + i * 256;          // 0..511
            int kk  = idx >> 4;               // 0..31
            int cq  = idx & 15;               // 0..15
            *reinterpret_cast<float4*>(&Bs[kk][cq * 4]) =
                *reinterpret_cast<const float4*>(W + (size_t)(k0 + kk) * HEAD + cq * 4);
        }
        __syncthreads();

        #pragma unroll 8
        for (int kk = 0; kk < 32; kk++) {
            float4 a = *reinterpret_cast<const float4*>(&As[kk][ty * 4]);
            float4 b = *reinterpret_cast<const float4*>(&Bs[kk][tx * 4]);
            acc[0][0] += a.x * b.x; acc[0][1] += a.x * b.y; acc[0][2] += a.x * b.z; acc[0][3] += a.x * b.w;
            acc[1][0] += a.y * b.x; acc[1][1] += a.y * b.y; acc[1][2] += a.y * b.z; acc[1][3] += a.y * b.w;
            acc[2][0] += a.z * b.x; acc[2][1] += a.z * b.y; acc[2][2] += a.z * b.z; acc[2][3] += a.z * b.w;
            acc[3][0] += a.w * b.x; acc[3][1] += a.w * b.y; acc[3][2] += a.w * b.z; acc[3][3] += a.w * b.w;
        }
        __syncthreads();
    }

    #pragma unroll
    for (int i = 0; i < 4; i++) {
        float4 r = make_float4(acc[i][0], acc[i][1], acc[i][2], acc[i][3]);
        *reinterpret_cast<float4*>(out + (size_t)(row0 + ty * 4 + i) * HEAD + tx * 4) = r;
    }
}

// ---------------------------------------------------------------------------
// Kernel 2: flash attention per (q-tile 64, batch). grid = (32, 8), block 256.
// Mask is int32 (nonzero = attend).
// ---------------------------------------------------------------------------
__global__ __launch_bounds__(256) void attn_kernel(
    const int* __restrict__ mask, float* __restrict__ out)
{
    const int b  = blockIdx.y;
    const int q0 = blockIdx.x * 64;
    const float* __restrict__ qp = g_qp + (size_t)b * SEQ * HEAD;
    const float* __restrict__ kp = g_kp + (size_t)b * SEQ * HEAD;
    const float* __restrict__ vp = g_vp + (size_t)b * SEQ * HEAD;

    extern __shared__ float sm[];
    float* Qs = sm;                 // [64 h][68 q] (transposed, padded)
    float* Ks = Qs + 64 * 68;       // [64 h][68 k]
    float* Vs = Ks + 64 * 68;       // [64 k][64 h]
    float* Ps = Vs + 64 * 64;       // [64 k][68 q]
    __shared__ float biasS[64];

    const int tid = threadIdx.x;
    const int tx = tid & 15;        // key-col group in S phase / h-col group in PV
    const int ty = tid >> 4;        // q-row group

    // Load Q tile transposed & pre-scaled
    #pragma unroll
    for (int i = 0; i < 4; i++) {
        int idx = tid + i * 256;    // 0..1023
        int qr  = idx >> 4;         // 0..63
        int hq  = idx & 15;         // 0..15
        float4 t = *reinterpret_cast<const float4*>(qp + (size_t)(q0 + qr) * HEAD + hq * 4);
        Qs[(hq * 4 + 0) * 68 + qr] = t.x * SCALE;
        Qs[(hq * 4 + 1) * 68 + qr] = t.y * SCALE;
        Qs[(hq * 4 + 2) * 68 + qr] = t.z * SCALE;
        Qs[(hq * 4 + 3) * 68 + qr] = t.w * SCALE;
    }

    const float NEG_INF = __int_as_float(0xff800000);
    float m[4] = {NEG_INF, NEG_INF, NEG_INF, NEG_INF};
    float l[4] = {0.f, 0.f, 0.f, 0.f};
    float o[4][4] = {};

    for (int kt = 0; kt < SEQ / 64; kt++) {
        const int k0 = kt * 64;

        #pragma unroll
        for (int i = 0; i < 4; i++) {
            int idx = tid + i * 256;
            int kr  = idx >> 4;
            int hq  = idx & 15;
            float4 t = *reinterpret_cast<const float4*>(kp + (size_t)(k0 + kr) * HEAD + hq * 4);
            Ks[(hq * 4 + 0) * 68 + kr] = t.x;
            Ks[(hq * 4 + 1) * 68 + kr] = t.y;
            Ks[(hq * 4 + 2) * 68 + kr] = t.z;
            Ks[(hq * 4 + 3) * 68 + kr] = t.w;
            float4 u = *reinterpret_cast<const float4*>(vp + (size_t)(k0 + kr) * HEAD + hq * 4);
            *reinterpret_cast<float4*>(&Vs[kr * 64 + hq * 4]) = u;
        }
        if (tid < 64)
            biasS[tid] = (mask[(size_t)b * SEQ + k0 + tid] != 0) ? 0.f : -1e30f;
        __syncthreads();

        // S = (Q*scale) @ K^T
        float s[4][4] = {};
        #pragma unroll 8
        for (int h = 0; h < 64; h++) {
            float4 a = *reinterpret_cast<const float4*>(&Qs[h * 68 + ty * 4]);
            float4 kb = *reinterpret_cast<const float4*>(&Ks[h * 68 + tx * 4]);
            s[0][0] += a.x * kb.x; s[0][1] += a.x * kb.y; s[0][2] += a.x * kb.z; s[0][3] += a.x * kb.w;
            s[1][0] += a.y * kb.x; s[1][1] += a.y * kb.y; s[1][2] += a.y * kb.z; s[1][3] += a.y * kb.w;
            s[2][0] += a.z * kb.x; s[2][1] += a.z * kb.y; s[2][2] += a.z * kb.z; s[2][3] += a.z * kb.w;
            s[3][0] += a.w * kb.x; s[3][1] += a.w * kb.y; s[3][2] += a.w * kb.z; s[3][3] += a.w * kb.w;
        }

        // mask bias + online softmax (row reduce across the 16 tx lanes)
        #pragma unroll
        for (int i = 0; i < 4; i++) {
            float p0 = s[i][0] + biasS[tx * 4 + 0];
            float p1 = s[i][1] + biasS[tx * 4 + 1];
            float p2 = s[i][2] + biasS[tx * 4 + 2];
            float p3 = s[i][3] + biasS[tx * 4 + 3];
            float mx = fmaxf(fmaxf(p0, p1), fmaxf(p2, p3));
            #pragma unroll
            for (int off = 1; off < 16; off <<= 1)
                mx = fmaxf(mx, __shfl_xor_sync(0xffffffffu, mx, off));
            float m_new = fmaxf(m[i], mx);
            float alpha = __expf(m[i] - m_new);
            p0 = __expf(p0 - m_new);
            p1 = __expf(p1 - m_new);
            p2 = __expf(p2 - m_new);
            p3 = __expf(p3 - m_new);
            float rs = p0 + p1 + p2 + p3;
            #pragma unroll
            for (int off = 1; off < 16; off <<= 1)
                rs += __shfl_xor_sync(0xffffffffu, rs, off);
            l[i] = l[i] * alpha + rs;
            m[i] = m_new;
            o[i][0] *= alpha; o[i][1] *= alpha; o[i][2] *= alpha; o[i][3] *= alpha;
            Ps[(tx * 4 + 0) * 68 + ty * 4 + i] = p0;
            Ps[(tx * 4 + 1) * 68 + ty * 4 + i] = p1;
            Ps[(tx * 4 + 2) * 68 + ty * 4 + i] = p2;
            Ps[(tx * 4 + 3) * 68 + ty * 4 + i] = p3;
        }
        __syncthreads();

        // O += P @ V
        #pragma unroll 8
        for (int kk = 0; kk < 64; kk++) {
            float4 a = *reinterpret_cast<const float4*>(&Ps[kk * 68 + ty * 4]);
            float4 vb = *reinterpret_cast<const float4*>(&Vs[kk * 64 + tx * 4]);
            o[0][0] += a.x * vb.x; o[0][1] += a.x * vb.y; o[0][2] += a.x * vb.z; o[0][3] += a.x * vb.w;
            o[1][0] += a.y * vb.x; o[1][1] += a.y * vb.y; o[1][2] += a.y * vb.z; o[1][3] += a.y * vb.w;
            o[2][0] += a.z * vb.x; o[2][1] += a.z * vb.y; o[2][2] += a.z * vb.z; o[2][3] += a.z * vb.w;
            o[3][0] += a.w * vb.x; o[3][1] += a.w * vb.y; o[3][2] += a.w * vb.z; o[3][3] += a.w * vb.w;
        }
        __syncthreads();
    }

    #pragma unroll
    for (int i = 0; i < 4; i++) {
        float inv = 1.0f / l[i];
        float4 r = make_float4(o[i][0] * inv, o[i][1] * inv, o[i][2] * inv, o[i][3] * inv);
        *reinterpret_cast<float4*>(out + (size_t)(b * SEQ + q0 + ty * 4 + i) * HEAD + tx * 4) = r;
    }
}

// ---------------------------------------------------------------------------
extern "C" void kernel_launch(void* const* d_in, const int* in_sizes, int n_in,
                              void* d_out, int out_size)
{
    // Robust binding by element count (preserves relative order within class):
    //   16777216 -> q, k, v    65536 -> Wq, Wk, Wv    16384 -> mask
    const void* big[3]   = {0, 0, 0};
    const void* small[3] = {0, 0, 0};
    const void* mk = 0;
    int nb = 0, ns = 0;
    for (int i = 0; i < n_in; i++) {
        if (in_sizes[i] == NROWS * DEMB)      { if (nb < 3) big[nb++] = d_in[i]; }
        else if (in_sizes[i] == DEMB * HEAD)  { if (ns < 3) small[ns++] = d_in[i]; }
        else if (in_sizes[i] == BATCH * SEQ)  { mk = d_in[i]; }
    }
    const float* q  = (const float*)big[0];
    const float* k  = (const float*)big[1];
    const float* v  = (const float*)big[2];
    const float* Wq = (const float*)small[0];
    const float* Wk = (const float*)small[1];
    const float* Wv = (const float*)small[2];
    const int*   mask = (const int*)mk;
    float* out = (float*)d_out;

    proj_kernel<<<dim3(NROWS / 64, 3), 256>>>(q, k, v, Wq, Wk, Wv);

    const int smem = (64 * 68 * 2 + 64 * 64 + 64 * 68) * (int)sizeof(float); // ~68.6 KB
    static bool attr_set = false;
    if (!attr_set) {
        cudaFuncSetAttribute(attn_kernel, cudaFuncAttributeMaxDynamicSharedMemorySize, smem);
        attr_set = true;
    }
    attn_kernel<<<dim3(SEQ / 64, BATCH), 256, smem>>>(mask, out);
}